// round 15
// baseline (speedup 1.0000x reference)
#include <cuda_runtime.h>
#include <cstdint>
#include <cstddef>

// ---------------------------------------------------------------------------
// GRU stack: 4 layers (256 -> 256), B=128, T=384, reset_after=True (Keras).
// Phase A (per layer): xp = X @ W + b_in   (fp32 GEMM, scalar FFMA, dbl-buffer)
// Phase B (per layer): persistent scan, 8-CTA clusters per 8-row batch tile.
//   WARP-SPECIALIZED: warps 0-3 run rows 0-3 (tile A), warps 4-7 run rows 4-7
//   (tile B) as two independent scans sharing the SMEM weight slice. Separate
//   mbarriers + named barriers per tile; the scheduler overlaps one tile's
//   sync stalls with the other tile's compute.
// ---------------------------------------------------------------------------

#define BATCH   128
#define T_STEPS 384
#define UNITS   256
#define G3      768
#define MROWS   (BATCH * T_STEPS)   // 49152

__device__ float g_xp[MROWS * G3];      // [B*T, 768] input projections
__device__ float g_hseq[MROWS * UNITS]; // [B*T, 256] hidden sequence

// ---------------------------------------------------------------------------
typedef unsigned long long ull;

__device__ __forceinline__ ull p2(float x, float y) {
    ull d; asm("mov.b64 %0, {%1, %2};" : "=l"(d) : "f"(x), "f"(y)); return d;
}
__device__ __forceinline__ ull p1(float x) {
    ull d; asm("mov.b64 %0, {%1, %1};" : "=l"(d) : "f"(x)); return d;
}
__device__ __forceinline__ void fma2(ull& acc, ull a, ull b) {
    asm("fma.rn.f32x2 %0, %1, %2, %0;" : "+l"(acc) : "l"(a), "l"(b));
}
__device__ __forceinline__ void add2(ull& acc, ull a) {
    asm("add.rn.f32x2 %0, %1, %0;" : "+l"(acc) : "l"(a));
}
__device__ __forceinline__ float2 unp2(ull d) {
    float2 v; asm("mov.b64 {%0, %1}, %2;" : "=f"(v.x), "=f"(v.y) : "l"(d)); return v;
}

// ---------------------------------------------------------------------------
__device__ __forceinline__ uint32_t smem_u32(const void* p) {
    uint32_t a;
    asm("{ .reg .u64 t; cvta.to.shared.u64 t, %1; cvt.u32.u64 %0, t; }"
        : "=r"(a) : "l"(p));
    return a;
}
__device__ __forceinline__ uint32_t mapa_u32(uint32_t a, uint32_t rank) {
    uint32_t r;
    asm("mapa.shared::cluster.u32 %0, %1, %2;" : "=r"(r) : "r"(a), "r"(rank));
    return r;
}
__device__ __forceinline__ void mbar_init(uint32_t a, uint32_t cnt) {
    asm volatile("mbarrier.init.shared.b64 [%0], %1;" :: "r"(a), "r"(cnt) : "memory");
}
__device__ __forceinline__ void mbar_expect(uint32_t a, uint32_t bytes) {
    asm volatile("mbarrier.arrive.expect_tx.shared.b64 _, [%0], %1;"
                 :: "r"(a), "r"(bytes) : "memory");
}
__device__ __forceinline__ void mbar_arrive_remote(uint32_t a) {
    asm volatile("mbarrier.arrive.shared::cluster.b64 _, [%0];" :: "r"(a) : "memory");
}
// deadman wait: pure fast spin, bounded; wedge -> garbage fast, never a hang.
__device__ __forceinline__ bool mbar_try_wait(uint32_t a, int parity) {
    unsigned ok = 0;
    for (int i = 0; i < 20000; i++) {
        asm volatile(
            "{\n\t.reg .pred P;\n\t"
            "mbarrier.try_wait.parity.acquire.cluster.shared::cta.b64 P, [%1], %2;\n\t"
            "selp.u32 %0, 1, 0, P;\n\t}"
            : "=r"(ok) : "r"(a), "r"((unsigned)parity) : "memory");
        if (ok) return true;
    }
    return false;
}
// s2s bulk: local SMEM -> peer CTA SMEM, complete_tx (bytes) on peer's mbar.
__device__ __forceinline__ void bulk_dsmem(uint32_t dst_cluster, uint32_t src_cta,
                                           uint32_t bytes, uint32_t rmbar_cluster) {
    asm volatile(
        "cp.async.bulk.shared::cluster.shared::cta.mbarrier::complete_tx::bytes "
        "[%0], [%1], %2, [%3];"
        :: "r"(dst_cluster), "r"(src_cta), "r"(bytes), "r"(rmbar_cluster) : "memory");
}
__device__ __forceinline__ void bar_named(int id) {
    asm volatile("bar.sync %0, 128;" :: "r"(id) : "memory");
}
#define CLUSTER_SYNC_() do {                                          \
    asm volatile("barrier.cluster.arrive.aligned;" ::: "memory");     \
    asm volatile("barrier.cluster.wait.aligned;" ::: "memory");       \
} while (0)

__device__ __forceinline__ float sigm_(float x) {
    return 1.f / (1.f + __expf(-x));
}
__device__ __forceinline__ float tanh_(float x) {
    float s = 1.f / (1.f + __expf(-2.f * x));
    return 2.f * s - 1.f;
}

// ---------------------------------------------------------------------------
// SGEMM: C[M=49152, N=768] = A[M,256] @ W[256,768] + bias_in[768]
// (Proven R2/R5 version: 359us, fma=67.5%, regs=125.)
// ---------------------------------------------------------------------------
__global__ __launch_bounds__(256, 2) void gemm_kernel(
    const float* __restrict__ X,
    const float* __restrict__ W,
    const float* __restrict__ bin,
    int use_x)
{
    const int K = 256, N = G3;
    const float* A = use_x ? X : g_hseq;

    __shared__ float As[2][8][128];
    __shared__ float Bs[2][8][128];

    int tid = threadIdx.x;
    int tx = tid & 15;
    int ty = tid >> 4;
    int bm = blockIdx.y * 128;
    int bn = blockIdx.x * 128;

    float acc[8][8];
#pragma unroll
    for (int i = 0; i < 8; i++)
#pragma unroll
        for (int j = 0; j < 8; j++) acc[i][j] = 0.f;

    int arow = tid >> 1;
    int acol = (tid & 1) * 4;
    int brow = tid >> 5;
    int bcol = (tid & 31) * 4;

    const float* Ap = A + (size_t)(bm + arow) * K + acol;
    const float* Wp = W + (size_t)brow * N + bn + bcol;

    {
        float4 a4 = *(const float4*)(Ap);
        float4 b4 = *(const float4*)(Wp);
        As[0][acol + 0][arow] = a4.x;
        As[0][acol + 1][arow] = a4.y;
        As[0][acol + 2][arow] = a4.z;
        As[0][acol + 3][arow] = a4.w;
        *(float4*)&Bs[0][brow][bcol] = b4;
    }
    __syncthreads();

    int buf = 0;
    for (int k0 = 8; k0 <= K; k0 += 8) {
        float4 a4n, b4n;
        if (k0 < K) {
            a4n = *(const float4*)(Ap + k0);
            b4n = *(const float4*)(Wp + (size_t)k0 * N);
        }
#pragma unroll
        for (int kk = 0; kk < 8; kk++) {
            float ra[8], rb[8];
            *(float4*)(ra)     = *(const float4*)&As[buf][kk][ty * 4];
            *(float4*)(ra + 4) = *(const float4*)&As[buf][kk][64 + ty * 4];
            *(float4*)(rb)     = *(const float4*)&Bs[buf][kk][tx * 4];
            *(float4*)(rb + 4) = *(const float4*)&Bs[buf][kk][64 + tx * 4];
#pragma unroll
            for (int i = 0; i < 8; i++)
#pragma unroll
                for (int j = 0; j < 8; j++)
                    acc[i][j] += ra[i] * rb[j];
        }
        if (k0 < K) {
            int nb = buf ^ 1;
            As[nb][acol + 0][arow] = a4n.x;
            As[nb][acol + 1][arow] = a4n.y;
            As[nb][acol + 2][arow] = a4n.z;
            As[nb][acol + 3][arow] = a4n.w;
            *(float4*)&Bs[nb][brow][bcol] = b4n;
            __syncthreads();
            buf = nb;
        }
    }

#pragma unroll
    for (int i = 0; i < 8; i++) {
        int row = (i < 4) ? (ty * 4 + i) : (64 + ty * 4 + (i - 4));
#pragma unroll
        for (int jh = 0; jh < 2; jh++) {
            int col = jh * 64 + tx * 4;
            float4 v;
            v.x = acc[i][jh * 4 + 0] + bin[bn + col + 0];
            v.y = acc[i][jh * 4 + 1] + bin[bn + col + 1];
            v.z = acc[i][jh * 4 + 2] + bin[bn + col + 2];
            v.w = acc[i][jh * 4 + 3] + bin[bn + col + 3];
            *(float4*)&g_xp[(size_t)(bm + row) * N + bn + col] = v;
        }
    }
}

// ---------------------------------------------------------------------------
// Warp-specialized scan. Grid (8,16), cluster (8,1,1).
// smem (bytes):
//   mbar: fullA[2]@0,8  emptyA[2]@16,24  fullB[2]@32,40  emptyB[2]@48,56
//   OFF_W   : 6144 float4 = 98304 B  weight slice w4[kp][g][up] (shared A/B)
//   OFF_HA  : hA[2][64 kp][4 rows]f2 = 8192 ;  OFF_HB likewise
//   OFF_REDA: redA[4 ks][32 lane][7] ull = 7168 ; OFF_REDB likewise
//   OFF_STGA: stageA[2][512] ; OFF_STGB likewise
// Per-tile protocol = R10 (depth-2, fullp {0,0}, ep {0,1}, bulk push).
// ---------------------------------------------------------------------------
#define OFF_W    128
#define OFF_HA   98432
#define OFF_HB   106624
#define OFF_REDA 114816
#define OFF_REDB 121984
#define OFF_STGA 129152
#define OFF_STGB 130176
#define SCAN_SMEM (OFF_STGB + 1024)   // 131200

__global__ __launch_bounds__(256, 1) __cluster_dims__(8, 1, 1)
void scan_kernel(const float* __restrict__ RK,    // [256, 768]
                 const float* __restrict__ brec)  // [768]
{
    extern __shared__ char smem[];
    const int tid = threadIdx.x;
    const int ut = blockIdx.x;          // cluster rank (unit tile)
    const int bt = blockIdx.y;
    const int u0 = ut * 32;
    const int b0 = bt * 8;

    const uint32_t sbase = smem_u32(smem);
    float4* sW = (float4*)(smem + OFF_W);

    // weight fill (all 256 threads): w4[kp][g][up]
    for (int i = tid; i < 6144; i += 256) {
        int kp = i / 48;
        int rem = i - kp * 48;
        int g = rem >> 4;
        int up = rem & 15;
        const float* s0 = RK + (size_t)(2 * kp) * G3 + g * 256 + u0 + 2 * up;
        float2 a = *(const float2*)s0;
        float2 b = *(const float2*)(s0 + G3);
        sW[i] = make_float4(a.x, a.y, b.x, b.y);
    }
    // zero slot 0 of both h rings (h(-1) = 0)
    for (int i = tid; i < 512; i += 256) {
        ((float4*)(smem + OFF_HA))[i % 256 + (i >= 256 ? 0 : 0)] =
            make_float4(0, 0, 0, 0);   // placeholder overwritten below
    }
    // (explicit, simple zeroing)
    for (int i = tid; i < 256; i += 256) {
        ((float4*)(smem + OFF_HA))[i] = make_float4(0, 0, 0, 0);
        ((float4*)(smem + OFF_HB))[i] = make_float4(0, 0, 0, 0);
    }
    if (tid == 0) {
        mbar_init(sbase + 0, 1);    // fullA[0]
        mbar_init(sbase + 8, 1);    // fullA[1]
        mbar_init(sbase + 16, 8);   // emptyA[0]
        mbar_init(sbase + 24, 8);   // emptyA[1]
        mbar_init(sbase + 32, 1);   // fullB[0]
        mbar_init(sbase + 40, 1);   // fullB[1]
        mbar_init(sbase + 48, 8);   // emptyB[0]
        mbar_init(sbase + 56, 8);   // emptyB[1]
        asm volatile("fence.mbarrier_init.release.cluster;" ::: "memory");
        mbar_expect(sbase + 8, 4096);    // pre-arm fullA[1] (h(0) fill)
        mbar_expect(sbase + 40, 4096);   // pre-arm fullB[1]
    }
    __syncthreads();
    CLUSTER_SYNC_();

    const int tile = tid >> 7;          // 0 = rows b0..b0+3, 1 = b0+4..b0+7
    const int htid = tid & 127;
    const int ks = htid >> 5;           // 0..3 k-split (64 k each)
    const int lane = htid & 31;
    const int bg = lane >> 4;           // row pair {2bg, 2bg+1}
    const int up = lane & 15;           // unit pair
    const int barid = 1 + tile;

    const uint32_t mb_full  = sbase + tile * 32;        // + v*8
    const uint32_t mb_empty = sbase + tile * 32 + 16;   // + v*8
    const int off_h  = (tile ? OFF_HB : OFF_HA);
    const int off_st = (tile ? OFF_STGB : OFF_STGA);
    ull* red = (ull*)(smem + (tile ? OFF_REDB : OFF_REDA));

    const int fb = htid >> 4;           // finalists (htid < 64): local row 0..3
    const int fu = htid & 15;
    const int bgF = fb >> 1;
    const int rF = fb & 1;
    const int growF = b0 + tile * 4 + fb;   // global batch row

    float2 bzv = make_float2(0, 0), brv = make_float2(0, 0), bhv = make_float2(0, 0);
    if (htid < 64) {
        bzv = *(const float2*)(brec + 0   + u0 + 2 * fu);
        brv = *(const float2*)(brec + 256 + u0 + 2 * fu);
        bhv = *(const float2*)(brec + 512 + u0 + 2 * fu);
    }

    int fullp[2] = {0, 0};
    int ep[2] = {0, 1};      // R4/R10-validated parity init
    int dead = 0;

    for (int t = 0; t < T_STEPS; t++) {
        const int v = t & 1;        // slot holding h(t-1)
        const int w = v ^ 1;        // slot receiving h(t)

        // prefetch xp(t) before waiting
        float2 mzv, mrv, mhv;
        if (htid < 64) {
            const float* xr = g_xp + ((size_t)growF * T_STEPS + t) * G3;
            mzv = *(const float2*)(xr + 0   + u0 + 2 * fu);
            mrv = *(const float2*)(xr + 256 + u0 + 2 * fu);
            mhv = *(const float2*)(xr + 512 + u0 + 2 * fu);
        }

        if (t > 0) {
            if (!dead && !mbar_try_wait(mb_full + v * 8, fullp[v])) dead = 1;
            fullp[v] ^= 1;
        }

        // partial GEMM: this thread's 32 k-pairs for 2 rows x 1 unit pair x 3g
        ull acc[2][3];
#pragma unroll
        for (int r = 0; r < 2; r++)
#pragma unroll
            for (int g = 0; g < 3; g++) acc[r][g] = 0ull;

        const char* hbuf = smem + off_h + v * 4096;
        const int kp0 = ks * 32;
#pragma unroll 8
        for (int kp = kp0; kp < kp0 + 32; kp++) {
            float4 h4 = *(const float4*)(hbuf + kp * 32 + bg * 16);
            ull h0a = p1(h4.x), h1a = p1(h4.y);   // row 2bg   (k 2kp, 2kp+1)
            ull h0b = p1(h4.z), h1b = p1(h4.w);   // row 2bg+1
#pragma unroll
            for (int g = 0; g < 3; g++) {
                float4 wv = sW[kp * 48 + g * 16 + up];
                ull w01 = p2(wv.x, wv.y);
                ull w23 = p2(wv.z, wv.w);
                fma2(acc[0][g], h0a, w01);
                fma2(acc[0][g], h1a, w23);
                fma2(acc[1][g], h0b, w01);
                fma2(acc[1][g], h1b, w23);
            }
        }

        // own h_prev (read slot v before releasing it)
        float2 hp = make_float2(0, 0);
        if (htid < 64)
            hp = *(const float2*)(hbuf + (ut * 16 + fu) * 32 + fb * 8);

        {
            ull* my = red + (size_t)(ks * 32 + lane) * 7;
#pragma unroll
            for (int g = 0; g < 3; g++) {
                my[g * 2 + 0] = acc[0][g];
                my[g * 2 + 1] = acc[1][g];
            }
        }
        bar_named(barid);

        // slot v consumed: arm its next fill + release empty (non-finalist thread)
        if (htid == 64 && t <= T_STEPS - 3) {
            mbar_expect(mb_full + v * 8, 4096);
            uint32_t emb = mb_empty + v * 8;
#pragma unroll
            for (int c = 0; c < 8; c++)
                mbar_arrive_remote(mapa_u32(emb, c));
        }

        if (htid < 64) {
            ull s[3];
#pragma unroll
            for (int g = 0; g < 3; g++) {
                ull a = red[(size_t)(bgF * 16 + fu) * 7 + g * 2 + rF];
#pragma unroll
                for (int k2 = 1; k2 < 4; k2++)
                    add2(a, red[(size_t)(k2 * 32 + bgF * 16 + fu) * 7 + g * 2 + rF]);
                s[g] = a;
            }
            float2 az = unp2(s[0]);
            float2 ar = unp2(s[1]);
            float2 ah = unp2(s[2]);

            float z0 = sigm_(mzv.x + az.x + bzv.x);
            float r0 = sigm_(mrv.x + ar.x + brv.x);
            float c0 = tanh_(mhv.x + r0 * (ah.x + bhv.x));
            float hn0 = z0 * hp.x + (1.f - z0) * c0;

            float z1 = sigm_(mzv.y + az.y + bzv.y);
            float r1 = sigm_(mrv.y + ar.y + brv.y);
            float c1 = tanh_(mhv.y + r1 * (ah.y + bhv.y));
            float hn1 = z1 * hp.y + (1.f - z1) * c1;

            *(float2*)(g_hseq + ((size_t)growF * T_STEPS + t) * UNITS + u0 + 2 * fu)
                = make_float2(hn0, hn1);

            // stage h(t); stage[w] reuse guarded by empty[w] (R10 logic)
            if (t <= T_STEPS - 2) {
                if (!dead && !mbar_try_wait(mb_empty + w * 8, ep[w])) dead = 1;
                ep[w] ^= 1;
                *(float2*)(smem + off_st + w * 512 + fu * 32 + fb * 8)
                    = make_float2(hn0, hn1);
            }
        }
        bar_named(barid);

        if (t <= T_STEPS - 2 && htid == 64) {
            asm volatile("fence.proxy.async.shared::cta;" ::: "memory");
            uint32_t src = sbase + off_st + w * 512;
            uint32_t dl  = sbase + off_h + w * 4096 + ut * 512;
            uint32_t ml  = mb_full + w * 8;   // peer's full[w]
#pragma unroll
            for (int c = 0; c < 8; c++)
                bulk_dsmem(mapa_u32(dl, c), src, 512, mapa_u32(ml, c));
        }
    }
    CLUSTER_SYNC_();
}

// ---------------------------------------------------------------------------
__global__ void copy_out_kernel(float* __restrict__ out) {
    int i = blockIdx.x * 256 + threadIdx.x;
    int b = i >> 8;
    int u = i & 255;
    out[i] = g_hseq[((size_t)b * T_STEPS + (T_STEPS - 1)) * UNITS + u];
}

// ---------------------------------------------------------------------------
extern "C" void kernel_launch(void* const* d_in, const int* in_sizes, int n_in,
                              void* d_out, int out_size) {
    (void)in_sizes; (void)n_in; (void)out_size;
    const float* x     = (const float*)d_in[0];
    const float* k0    = (const float*)d_in[1];
    const float* rk0   = (const float*)d_in[2];
    const float* b0    = (const float*)d_in[3];
    const float* kern  = (const float*)d_in[4];
    const float* rkern = (const float*)d_in[5];
    const float* bias  = (const float*)d_in[6];
    float* out = (float*)d_out;

    cudaFuncSetAttribute(scan_kernel,
        cudaFuncAttributeMaxDynamicSharedMemorySize, SCAN_SMEM);

    dim3 ggrid(G3 / 128, MROWS / 128);
    dim3 sgrid(8, 16);

    gemm_kernel<<<ggrid, 256>>>(x, k0, b0, 1);
    scan_kernel<<<sgrid, 256, SCAN_SMEM>>>(rk0, b0 + G3);

    for (int l = 0; l < 3; l++) {
        gemm_kernel<<<ggrid, 256>>>(nullptr, kern + (size_t)l * 256 * G3,
                                    bias + (size_t)l * 2 * G3, 0);
        scan_kernel<<<sgrid, 256, SCAN_SMEM>>>(rkern + (size_t)l * 256 * G3,
                                    bias + (size_t)l * 2 * G3 + G3);
    }

    copy_out_kernel<<<BATCH, 256>>>(out);
}

// round 17
// speedup vs baseline: 1.1350x; 1.1350x over previous
#include <cuda_runtime.h>
#include <cstdint>
#include <cstddef>

// ---------------------------------------------------------------------------
// GRU stack: 4 layers (256 -> 256), B=128, T=384, reset_after=True (Keras).
// Phase A (per layer): xp = X @ W + b_in  -- f32x2 GEMM, 128x64 tile (no spills)
// Phase B (per layer): persistent scan, 8-CTA clusters, depth-4 h ring,
//                      8 x 1KB s2s bulk broadcast (best measured: 8689.9us).
// ---------------------------------------------------------------------------

#define BATCH   128
#define T_STEPS 384
#define UNITS   256
#define G3      768
#define MROWS   (BATCH * T_STEPS)   // 49152

__device__ float g_xp[MROWS * G3];      // [B*T, 768] input projections
__device__ float g_hseq[MROWS * UNITS]; // [B*T, 256] hidden sequence

// ---------------------------------------------------------------------------
typedef unsigned long long ull;

__device__ __forceinline__ ull p2(float x, float y) {
    ull d; asm("mov.b64 %0, {%1, %2};" : "=l"(d) : "f"(x), "f"(y)); return d;
}
__device__ __forceinline__ ull p1(float x) {
    ull d; asm("mov.b64 %0, {%1, %1};" : "=l"(d) : "f"(x)); return d;
}
__device__ __forceinline__ void fma2(ull& acc, ull a, ull b) {
    asm("fma.rn.f32x2 %0, %1, %2, %0;" : "+l"(acc) : "l"(a), "l"(b));
}
__device__ __forceinline__ void add2(ull& acc, ull a) {
    asm("add.rn.f32x2 %0, %1, %0;" : "+l"(acc) : "l"(a));
}
__device__ __forceinline__ float2 unp2(ull d) {
    float2 v; asm("mov.b64 {%0, %1}, %2;" : "=f"(v.x), "=f"(v.y) : "l"(d)); return v;
}

// ---------------------------------------------------------------------------
__device__ __forceinline__ uint32_t smem_u32(const void* p) {
    uint32_t a;
    asm("{ .reg .u64 t; cvta.to.shared.u64 t, %1; cvt.u32.u64 %0, t; }"
        : "=r"(a) : "l"(p));
    return a;
}
__device__ __forceinline__ uint32_t mapa_u32(uint32_t a, uint32_t rank) {
    uint32_t r;
    asm("mapa.shared::cluster.u32 %0, %1, %2;" : "=r"(r) : "r"(a), "r"(rank));
    return r;
}
__device__ __forceinline__ void mbar_init(uint32_t a, uint32_t cnt) {
    asm volatile("mbarrier.init.shared.b64 [%0], %1;" :: "r"(a), "r"(cnt) : "memory");
}
__device__ __forceinline__ void mbar_expect(uint32_t a, uint32_t bytes) {
    asm volatile("mbarrier.arrive.expect_tx.shared.b64 _, [%0], %1;"
                 :: "r"(a), "r"(bytes) : "memory");
}
__device__ __forceinline__ void mbar_arrive_remote(uint32_t a) {
    asm volatile("mbarrier.arrive.shared::cluster.b64 _, [%0];" :: "r"(a) : "memory");
}
// deadman wait: pure fast spin, bounded; wedge -> garbage fast, never a hang.
__device__ __forceinline__ bool mbar_try_wait(uint32_t a, int parity) {
    unsigned ok = 0;
    for (int i = 0; i < 20000; i++) {
        asm volatile(
            "{\n\t.reg .pred P;\n\t"
            "mbarrier.try_wait.parity.acquire.cluster.shared::cta.b64 P, [%1], %2;\n\t"
            "selp.u32 %0, 1, 0, P;\n\t}"
            : "=r"(ok) : "r"(a), "r"((unsigned)parity) : "memory");
        if (ok) return true;
    }
    return false;
}
// s2s bulk: local SMEM -> peer CTA SMEM, complete_tx (bytes) on peer's mbar.
__device__ __forceinline__ void bulk_dsmem(uint32_t dst_cluster, uint32_t src_cta,
                                           uint32_t bytes, uint32_t rmbar_cluster) {
    asm volatile(
        "cp.async.bulk.shared::cluster.shared::cta.mbarrier::complete_tx::bytes "
        "[%0], [%1], %2, [%3];"
        :: "r"(dst_cluster), "r"(src_cta), "r"(bytes), "r"(rmbar_cluster) : "memory");
}
#define CLUSTER_SYNC_() do {                                          \
    asm volatile("barrier.cluster.arrive.aligned;" ::: "memory");     \
    asm volatile("barrier.cluster.wait.aligned;" ::: "memory");       \
} while (0)

__device__ __forceinline__ float sigm_(float x) {
    return 1.f / (1.f + __expf(-x));
}
__device__ __forceinline__ float tanh_(float x) {
    float s = 1.f / (1.f + __expf(-2.f * x));
    return 2.f * s - 1.f;
}

// ---------------------------------------------------------------------------
// SGEMM f32x2: C[M=49152, N=768] = A[M,256] @ W[256,768] + bias_in[768]
// 128x64x8 tiles, 256 threads, per-thread 8 rows x 4 cols (8x2 ull acc).
// ~90 regs -> no spills at 2 CTAs/SM. FMA-instruction count halved vs scalar.
// ---------------------------------------------------------------------------
__global__ __launch_bounds__(256, 2) void gemm_kernel(
    const float* __restrict__ X,
    const float* __restrict__ W,
    const float* __restrict__ bin,
    int use_x)
{
    const int K = 256, N = G3;
    const float* A = use_x ? X : g_hseq;

    __shared__ float As[2][8][128];
    __shared__ float Bs[2][8][64];

    int tid = threadIdx.x;
    int tx = tid & 15;          // 16 col groups x 4 cols
    int ty = tid >> 4;          // 16 row groups x (4+4) rows
    int bm = blockIdx.y * 128;
    int bn = blockIdx.x * 64;

    ull acc[8][2];
#pragma unroll
    for (int i = 0; i < 8; i++) { acc[i][0] = 0ull; acc[i][1] = 0ull; }

    int arow = tid >> 1;            // 0..127
    int acol = (tid & 1) * 4;       // 0 or 4
    const float* Ap = A + (size_t)(bm + arow) * K + acol;

    // B loaders: first 128 threads, one float4 each (8 k-rows x 64 cols)
    int brow = tid >> 4;            // 0..7  (tid<128)
    int bcol = (tid & 15) * 4;      // 0..60
    const float* Wp = W + (size_t)brow * N + bn + bcol;

    {
        float4 a4 = *(const float4*)(Ap);
        As[0][acol + 0][arow] = a4.x;
        As[0][acol + 1][arow] = a4.y;
        As[0][acol + 2][arow] = a4.z;
        As[0][acol + 3][arow] = a4.w;
        if (tid < 128) {
            float4 b4 = *(const float4*)(Wp);
            *(float4*)&Bs[0][brow][bcol] = b4;
        }
    }
    __syncthreads();

    int buf = 0;
    for (int k0 = 8; k0 <= K; k0 += 8) {
        float4 a4n, b4n;
        if (k0 < K) {
            a4n = *(const float4*)(Ap + k0);
            if (tid < 128) b4n = *(const float4*)(Wp + (size_t)k0 * N);
        }
#pragma unroll
        for (int kk = 0; kk < 8; kk++) {
            float4 aA = *(const float4*)&As[buf][kk][ty * 4];
            float4 aB = *(const float4*)&As[buf][kk][64 + ty * 4];
            float4 bA = *(const float4*)&Bs[buf][kk][tx * 4];
            ull rb0 = p2(bA.x, bA.y);
            ull rb1 = p2(bA.z, bA.w);
            ull ra;
            ra = p1(aA.x); fma2(acc[0][0], ra, rb0); fma2(acc[0][1], ra, rb1);
            ra = p1(aA.y); fma2(acc[1][0], ra, rb0); fma2(acc[1][1], ra, rb1);
            ra = p1(aA.z); fma2(acc[2][0], ra, rb0); fma2(acc[2][1], ra, rb1);
            ra = p1(aA.w); fma2(acc[3][0], ra, rb0); fma2(acc[3][1], ra, rb1);
            ra = p1(aB.x); fma2(acc[4][0], ra, rb0); fma2(acc[4][1], ra, rb1);
            ra = p1(aB.y); fma2(acc[5][0], ra, rb0); fma2(acc[5][1], ra, rb1);
            ra = p1(aB.z); fma2(acc[6][0], ra, rb0); fma2(acc[6][1], ra, rb1);
            ra = p1(aB.w); fma2(acc[7][0], ra, rb0); fma2(acc[7][1], ra, rb1);
        }
        if (k0 < K) {
            int nb = buf ^ 1;
            As[nb][acol + 0][arow] = a4n.x;
            As[nb][acol + 1][arow] = a4n.y;
            As[nb][acol + 2][arow] = a4n.z;
            As[nb][acol + 3][arow] = a4n.w;
            if (tid < 128) *(float4*)&Bs[nb][brow][bcol] = b4n;
            __syncthreads();
            buf = nb;
        }
    }

    float4 bv = *(const float4*)(bin + bn + tx * 4);
#pragma unroll
    for (int i = 0; i < 8; i++) {
        int row = (i < 4) ? (ty * 4 + i) : (64 + ty * 4 + (i - 4));
        float2 pa = unp2(acc[i][0]);
        float2 pb = unp2(acc[i][1]);
        float4 v;
        v.x = pa.x + bv.x;
        v.y = pa.y + bv.y;
        v.z = pb.x + bv.z;
        v.w = pb.y + bv.w;
        *(float4*)&g_xp[(size_t)(bm + row) * N + bn + tx * 4] = v;
    }
}

// ---------------------------------------------------------------------------
// Recurrent scan, depth-4 h ring (exact 8689.9us version — UNCHANGED).
// ---------------------------------------------------------------------------
#define OFF_W    128
#define OFF_H    98432
#define OFF_RED  131200
#define OFF_STG  157824
#define SCAN_SMEM (OFF_STG + 4096)   // 161920

__global__ __launch_bounds__(256, 1) __cluster_dims__(8, 1, 1)
void scan_kernel(const float* __restrict__ RK,    // [256, 768]
                 const float* __restrict__ brec)  // [768]
{
    extern __shared__ char smem[];
    const int tid = threadIdx.x;
    const int ut = blockIdx.x;          // cluster rank
    const int bt = blockIdx.y;
    const int u0 = ut * 32;
    const int b0 = bt * 8;

    const uint32_t sbase = smem_u32(smem);
    float4* sW = (float4*)(smem + OFF_W);
    ull* red = (ull*)(smem + OFF_RED);

    for (int i = tid; i < 6144; i += 256) {
        int kp = i / 48;
        int rem = i - kp * 48;
        int g = rem >> 4;
        int up = rem & 15;
        const float* s0 = RK + (size_t)(2 * kp) * G3 + g * 256 + u0 + 2 * up;
        float2 a = *(const float2*)s0;
        float2 b = *(const float2*)(s0 + G3);
        sW[i] = make_float4(a.x, a.y, b.x, b.y);
    }
    {
        float4* z = (float4*)(smem + OFF_H);
        for (int i = tid; i < 32768 / 16; i += 256) z[i] = make_float4(0, 0, 0, 0);
    }
    if (tid == 0) {
#pragma unroll
        for (int s = 0; s < 4; s++) {
            mbar_init(sbase + s * 8, 1);        // full[s]
            mbar_init(sbase + 32 + s * 8, 8);   // empty[s]
        }
        asm volatile("fence.mbarrier_init.release.cluster;" ::: "memory");
#pragma unroll
        for (int s = 0; s < 4; s++) mbar_expect(sbase + s * 8, 8192);
    }
    __syncthreads();
    CLUSTER_SYNC_();

    const int ks = tid >> 5;
    const int lane = tid & 31;
    const int bg = lane >> 4;
    const int up = lane & 15;
    const int kp0 = ks * 16;

    const int fb = tid >> 4;
    const int fu = tid & 15;
    const int bgF = fb >> 2;
    const int rF = fb & 3;

    float2 bzv = make_float2(0, 0), brv = make_float2(0, 0), bhv = make_float2(0, 0);
    if (tid < 128) {
        bzv = *(const float2*)(brec + 0   + u0 + 2 * fu);
        brv = *(const float2*)(brec + 256 + u0 + 2 * fu);
        bhv = *(const float2*)(brec + 512 + u0 + 2 * fu);
    }

    int dead = 0;

    for (int t = 0; t < T_STEPS; t++) {
        const int si = (t + 3) & 3;
        const int so = t & 3;

        float2 mzv, mrv, mhv;
        if (tid < 128) {
            const float* xr = g_xp + ((size_t)(b0 + fb) * T_STEPS + t) * G3;
            mzv = *(const float2*)(xr + 0   + u0 + 2 * fu);
            mrv = *(const float2*)(xr + 256 + u0 + 2 * fu);
            mhv = *(const float2*)(xr + 512 + u0 + 2 * fu);
        }

        if (t > 0) {
            int par = ((t - 1) >> 2) & 1;
            if (!dead && !mbar_try_wait(sbase + si * 8, par)) dead = 1;
        }

        ull acc[4][3];
#pragma unroll
        for (int r = 0; r < 4; r++)
#pragma unroll
            for (int g = 0; g < 3; g++) acc[r][g] = 0ull;

        const char* hbuf = smem + OFF_H + si * 8192;
#pragma unroll 4
        for (int kp = kp0; kp < kp0 + 16; kp++) {
            float4 hA = *(const float4*)(hbuf + kp * 64 + bg * 32);
            float4 hB = *(const float4*)(hbuf + kp * 64 + bg * 32 + 16);
            ull h0[4], h1[4];
            h0[0] = p1(hA.x); h1[0] = p1(hA.y);
            h0[1] = p1(hA.z); h1[1] = p1(hA.w);
            h0[2] = p1(hB.x); h1[2] = p1(hB.y);
            h0[3] = p1(hB.z); h1[3] = p1(hB.w);
#pragma unroll
            for (int g = 0; g < 3; g++) {
                float4 wv = sW[kp * 48 + g * 16 + up];
                ull w01 = p2(wv.x, wv.y);
                ull w23 = p2(wv.z, wv.w);
#pragma unroll
                for (int r = 0; r < 4; r++) {
                    fma2(acc[r][g], h0[r], w01);
                    fma2(acc[r][g], h1[r], w23);
                }
            }
        }

        float2 hp = make_float2(0, 0);
        if (tid < 128)
            hp = *(const float2*)(hbuf + ((ut * 16 + fu) * 8 + fb) * 8);

        {
            ull* my = red + (size_t)(ks * 32 + lane) * 13;
#pragma unroll
            for (int g = 0; g < 3; g++)
#pragma unroll
                for (int r = 0; r < 4; r++)
                    my[g * 4 + r] = acc[r][g];
        }
        __syncthreads();

        if (tid == 0 && t >= 1 && t <= T_STEPS - 5) {
            mbar_expect(sbase + si * 8, 8192);
            uint32_t emb = sbase + 32 + si * 8;
#pragma unroll
            for (int c = 0; c < 8; c++)
                mbar_arrive_remote(mapa_u32(emb, c));
        }

        if (tid < 128) {
            ull s[3];
#pragma unroll
            for (int g = 0; g < 3; g++) {
                ull a = red[(size_t)(bgF * 16 + fu) * 13 + g * 4 + rF];
#pragma unroll
                for (int k2 = 1; k2 < 8; k2++)
                    add2(a, red[(size_t)(k2 * 32 + bgF * 16 + fu) * 13 + g * 4 + rF]);
                s[g] = a;
            }
            float2 az = unp2(s[0]);
            float2 ar = unp2(s[1]);
            float2 ah = unp2(s[2]);

            float z0 = sigm_(mzv.x + az.x + bzv.x);
            float r0 = sigm_(mrv.x + ar.x + brv.x);
            float c0 = tanh_(mhv.x + r0 * (ah.x + bhv.x));
            float hn0 = z0 * hp.x + (1.f - z0) * c0;

            float z1 = sigm_(mzv.y + az.y + bzv.y);
            float r1 = sigm_(mrv.y + ar.y + brv.y);
            float c1 = tanh_(mhv.y + r1 * (ah.y + bhv.y));
            float hn1 = z1 * hp.y + (1.f - z1) * c1;

            *(float2*)(g_hseq + ((size_t)(b0 + fb) * T_STEPS + t) * UNITS + u0 + 2 * fu)
                = make_float2(hn0, hn1);

            if (t <= T_STEPS - 2) {
                if (t >= 4) {
                    int par = ((t >> 2) - 1) & 1;
                    if (!dead && !mbar_try_wait(sbase + 32 + so * 8, par)) dead = 1;
                }
                *(float2*)(smem + OFF_STG + so * 1024 + fu * 64 + fb * 8)
                    = make_float2(hn0, hn1);
            }
        }

        if (t <= T_STEPS - 2) {
            __syncthreads();
            if (tid == 0) {
                asm volatile("fence.proxy.async.shared::cta;" ::: "memory");
                uint32_t src = sbase + OFF_STG + so * 1024;
                uint32_t dl  = sbase + OFF_H + so * 8192 + ut * 1024;
                uint32_t ml  = sbase + so * 8;
#pragma unroll
                for (int c = 0; c < 8; c++)
                    bulk_dsmem(mapa_u32(dl, c), src, 1024, mapa_u32(ml, c));
            }
        }
    }
    CLUSTER_SYNC_();
}

// ---------------------------------------------------------------------------
__global__ void copy_out_kernel(float* __restrict__ out) {
    int i = blockIdx.x * 256 + threadIdx.x;
    int b = i >> 8;
    int u = i & 255;
    out[i] = g_hseq[((size_t)b * T_STEPS + (T_STEPS - 1)) * UNITS + u];
}

// ---------------------------------------------------------------------------
extern "C" void kernel_launch(void* const* d_in, const int* in_sizes, int n_in,
                              void* d_out, int out_size) {
    (void)in_sizes; (void)n_in; (void)out_size;
    const float* x     = (const float*)d_in[0];
    const float* k0    = (const float*)d_in[1];
    const float* rk0   = (const float*)d_in[2];
    const float* b0    = (const float*)d_in[3];
    const float* kern  = (const float*)d_in[4];
    const float* rkern = (const float*)d_in[5];
    const float* bias  = (const float*)d_in[6];
    float* out = (float*)d_out;

    cudaFuncSetAttribute(scan_kernel,
        cudaFuncAttributeMaxDynamicSharedMemorySize, SCAN_SMEM);

    dim3 ggrid(G3 / 64, MROWS / 128);    // (12, 384)
    dim3 sgrid(8, 16);

    gemm_kernel<<<ggrid, 256>>>(x, k0, b0, 1);
    scan_kernel<<<sgrid, 256, SCAN_SMEM>>>(rk0, b0 + G3);

    for (int l = 0; l < 3; l++) {
        gemm_kernel<<<ggrid, 256>>>(nullptr, kern + (size_t)l * 256 * G3,
                                    bias + (size_t)l * 2 * G3, 0);
        scan_kernel<<<sgrid, 256, SCAN_SMEM>>>(rkern + (size_t)l * 256 * G3,
                                    bias + (size_t)l * 2 * G3 + G3);
    }

    copy_out_kernel<<<BATCH, 256>>>(out);
}